// round 10
// baseline (speedup 1.0000x reference)
#include <cuda_runtime.h>
#include <math.h>

#define MBOX 512
#define CCH 512
#define POOLSZ 14
#define PP 196
#define HID 1024
#define NCLS 81
#define CONVO 256
#define KFC (CCH*PP)   /* 100352 */

#define BM 128
#define BN 128
#define BK 32
#define SPLITK 8
#define KPS (KFC/SPLITK)   /* 12544 */
#define KITERS (KPS/BK)    /* 392 */

#define BO 128   /* conv output-channel tile */

/* fc1 smem */
#define SA_STRIDE 36
#define SB_STRIDE 136
#define SA_BUF (BM*SA_STRIDE)
#define SB_BUF (BK*SB_STRIDE)
#define FC1_SMEM_BYTES ((2*SA_BUF + 2*SB_BUF)*4)   /* 71680 B */

/* conv smem: P padded to 9 words/pos (bank fix); P loads are 32-bit (alignment) */
#define WROW 76
#define W_BUF (BO*WROW)              /* 9728 floats */
#define PCH 9
#define P_BUF (256*PCH)              /* 2304 floats = 9216 B per slab */
#define CONV_SMEM_BYTES ((2*W_BUF + 2*P_BUF + BO)*4)  /* 96768 B */

// ---------------- scratch (static device globals) ----------------
__device__ float g_pooled[(size_t)MBOX*CCH*PP];        // tf32-rounded, flat (fc1)
__device__ float g_pp[(size_t)MBOX*64*256*PCH];        // tf32-rounded, [slab][pos][9]
__device__ float g_wT[(size_t)CONVO*4608];             // tf32-rounded, [o][slab][tap][chperm]
__device__ float g_hparts[SPLITK][(size_t)MBOX*HID];
__device__ float g_h[MBOX*HID];
__device__ float g_meanz[MBOX*CONVO];

// ---------------- helpers ----------------
__device__ __forceinline__ float tf32f(float x){
    unsigned u; asm("cvt.rna.tf32.f32 %0, %1;" : "=r"(u) : "f"(x));
    return __uint_as_float(u);
}
__device__ __forceinline__ unsigned tf32u(float x){
    unsigned u; asm("cvt.rna.tf32.f32 %0, %1;" : "=r"(u) : "f"(x));
    return u;
}
__device__ __forceinline__ void mma_tf32(float* c, const unsigned* a, const unsigned* b){
    asm volatile("mma.sync.aligned.m16n8k8.row.col.f32.tf32.tf32.f32 "
                 "{%0,%1,%2,%3},{%4,%5,%6,%7},{%8,%9},{%0,%1,%2,%3};\n"
                 : "+f"(c[0]), "+f"(c[1]), "+f"(c[2]), "+f"(c[3])
                 : "r"(a[0]), "r"(a[1]), "r"(a[2]), "r"(a[3]),
                   "r"(b[0]), "r"(b[1]));
}
__device__ __forceinline__ unsigned sptr(const void* p){
    return (unsigned)__cvta_generic_to_shared(p);
}
__device__ __forceinline__ void cpasync16(unsigned dst, const float* src){
    asm volatile("cp.async.cg.shared.global [%0], [%1], 16;" :: "r"(dst), "l"(src));
}
__device__ __forceinline__ void cp_commit(){ asm volatile("cp.async.commit_group;"); }
__device__ __forceinline__ void cp_wait0(){ asm volatile("cp.async.wait_group 0;"); }

__device__ __forceinline__ int chperm_of(int ch){ return (ch & 3)*2 + (ch >> 2); }

// ---------------- 1. RoIAlign (dual-layout write, pre-rounded) ----------------
__global__ void roialign_kernel(const float* __restrict__ p2, const float* __restrict__ p3,
                                const float* __restrict__ p4, const float* __restrict__ p5,
                                const float* __restrict__ boxes, const int* __restrict__ bidx,
                                const int* __restrict__ imh, const int* __restrict__ imw)
{
    int m = blockIdx.x;
    int cbase = blockIdx.y * 32;
    __shared__ float s_lx[POOLSZ], s_ly[POOLSZ];
    __shared__ int   s_x0[POOLSZ], s_x1[POOLSZ], s_y0[POOLSZ], s_y1[POOLSZ];
    __shared__ const float* s_feat;
    __shared__ int s_H, s_W;
    int tid = threadIdx.x;

    if (tid == 0){
        float bx1 = boxes[m*4+0], by1 = boxes[m*4+1];
        float bx2 = boxes[m*4+2], by2 = boxes[m*4+3];
        int hv = imh[0], wv = imw[0];
        float alpha = 224.0f/800.0f * (float)min(hv, wv);
        float bw = fabsf(bx2-bx1), bh = fabsf(by2-by1);
        float s  = sqrtf(fmaxf(bw*bh, 1e-6f));
        float kf = floorf(4.0f + log2f(s/alpha));
        int lvl  = (int)fminf(fmaxf(kf - 2.0f, 0.0f), 3.0f);
        const float* fp; int H, W; float scale;
        if      (lvl == 0){ fp = p2; H = 200; W = 200; scale = 0.25f; }
        else if (lvl == 1){ fp = p3; H = 100; W = 100; scale = 0.125f; }
        else if (lvl == 2){ fp = p4; H = 50;  W = 50;  scale = 0.0625f; }
        else              { fp = p5; H = 25;  W = 25;  scale = 0.03125f; }
        s_feat = fp; s_H = H; s_W = W;
        float sx1 = bx1*scale, sx2 = bx2*scale, sy1 = by1*scale, sy2 = by2*scale;
        for (int i = 0; i < POOLSZ; i++){
            float g  = ((float)i + 0.5f) / (float)POOLSZ;
            float xs = sx1 + g*(sx2 - sx1);
            float x0f = floorf(xs);
            s_lx[i] = xs - x0f;
            s_x0[i] = min(max((int)x0f, 0), W-1);
            s_x1[i] = min(max((int)x0f + 1, 0), W-1);
            float ys = sy1 + g*(sy2 - sy1);
            float y0f = floorf(ys);
            s_ly[i] = ys - y0f;
            s_y0[i] = min(max((int)y0f, 0), H-1);
            s_y1[i] = min(max((int)y0f + 1, 0), H-1);
        }
    }
    __syncthreads();

    const float* f = s_feat;
    int H = s_H, W = s_W;
    int b = bidx[m];

    // zero padded borders (ch words at border positions) for these 32 channels
    for (int e = tid; e < 32*256; e += blockDim.x){
        int ch = e >> 8, p = e & 255;
        int ty = p >> 4, tx = p & 15;
        if (ty == 0 || ty == 15 || tx == 0 || tx == 15){
            int c = cbase + ch;
            g_pp[(((size_t)m*64 + (c>>3))*256 + p)*PCH + chperm_of(c&7)] = 0.f;
        }
    }
    // zero the pad word (word 8) for this block's 4 slabs, all positions
    for (int e = tid; e < 4*256; e += blockDim.x){
        int sl = e >> 8, p = e & 255;
        g_pp[(((size_t)m*64 + (cbase>>3) + sl)*256 + p)*PCH + 8] = 0.f;
    }

    for (int e = tid; e < 32*PP; e += blockDim.x){
        int cl  = e / PP;
        int bin = e - cl*PP;
        int py  = bin / POOLSZ, px = bin - py*POOLSZ;
        int c   = cbase + cl;
        const float* fb = f + ((size_t)(b*CCH + c)) * H * W;
        float lx = s_lx[px], ly = s_ly[py];
        int x0 = s_x0[px], x1 = s_x1[px], y0 = s_y0[py], y1 = s_y1[py];
        float f00 = fb[y0*W + x0], f01 = fb[y0*W + x1];
        float f10 = fb[y1*W + x0], f11 = fb[y1*W + x1];
        float v = f00*(1.f-ly)*(1.f-lx) + f01*(1.f-ly)*lx
                + f10*ly*(1.f-lx)       + f11*ly*lx;
        float vr = tf32f(v);
        g_pooled[((size_t)m*CCH + c)*PP + bin] = vr;
        int pos = (py+1)*16 + (px+1);
        g_pp[(((size_t)m*64 + (c>>3))*256 + pos)*PCH + chperm_of(c&7)] = vr;
    }
}

// ---------------- 1b. conv weights: tap-major + k-pair interleave + tf32 round -----
__global__ void wtrans_kernel(const float* __restrict__ Wc){
    int i = blockIdx.x*256 + threadIdx.x;
    if (i < CONVO*4608){
        int o = i / 4608, k = i - o*4608;
        int slab = k / 72, r = k - slab*72;
        int tap = r >> 3, cp = r & 7;
        int ch = (cp >> 1) | ((cp & 1) << 2);
        g_wT[i] = tf32f(Wc[(size_t)o*4608 + (slab*8 + ch)*9 + tap]);
    }
}

// ---------------- 2. FC1 GEMM (tf32, cp.async double-buffered, split-K slices) -----
__global__ __launch_bounds__(256,2) void fc1_kernel(const float* __restrict__ Bw)
{
    extern __shared__ float sm[];
    float* bufA[2] = { sm,            sm + SA_BUF };
    float* bufB[2] = { sm + 2*SA_BUF, sm + 2*SA_BUF + SB_BUF };

    int tid = threadIdx.x, lane = tid & 31, warp = tid >> 5;
    int wm = warp >> 2, wn = warp & 3;
    int mbase = blockIdx.x * BM;
    int nbase = blockIdx.y * BN;
    int k0    = blockIdx.z * KPS;

    float acc[4][4][4];
    #pragma unroll
    for (int i = 0; i < 4; i++)
        #pragma unroll
        for (int j = 0; j < 4; j++)
            #pragma unroll
            for (int q = 0; q < 4; q++) acc[i][j][q] = 0.f;

    auto issue_tile = [&](int bi, int it){
        int koff = k0 + it*BK;
        #pragma unroll
        for (int j = 0; j < 4; j++){
            int cid = tid + j*256;
            int row = cid >> 3, c16 = (cid & 7)*4;
            cpasync16(sptr(bufA[bi] + row*SA_STRIDE + c16),
                      g_pooled + (size_t)(mbase+row)*KFC + koff + c16);
        }
        #pragma unroll
        for (int j = 0; j < 4; j++){
            int cid = tid + j*256;
            int row = cid >> 5, c16 = (cid & 31)*4;
            cpasync16(sptr(bufB[bi] + row*SB_STRIDE + c16),
                      Bw + (size_t)(koff+row)*HID + nbase + c16);
        }
        cp_commit();
    };

    issue_tile(0, 0);

    for (int it = 0; it < KITERS; it++){
        cp_wait0();
        __syncthreads();
        if (it + 1 < KITERS) issue_tile((it+1) & 1, it+1);

        const unsigned* cA = (const unsigned*)bufA[it & 1];
        const float*    cB = bufB[it & 1];
        #pragma unroll
        for (int ks = 0; ks < 4; ks++){
            unsigned a[4][4], bb[4][2];
            int kc = ks*8 + (lane & 3);
            #pragma unroll
            for (int mt = 0; mt < 4; mt++){
                int r = wm*64 + mt*16 + (lane >> 2);
                a[mt][0] = cA[(r  )*SA_STRIDE + kc  ];
                a[mt][1] = cA[(r+8)*SA_STRIDE + kc  ];
                a[mt][2] = cA[(r  )*SA_STRIDE + kc+4];
                a[mt][3] = cA[(r+8)*SA_STRIDE + kc+4];
            }
            #pragma unroll
            for (int nt = 0; nt < 4; nt++){
                int cidx = wn*32 + nt*8 + (lane >> 2);
                bb[nt][0] = tf32u(cB[(kc  )*SB_STRIDE + cidx]);
                bb[nt][1] = tf32u(cB[(kc+4)*SB_STRIDE + cidx]);
            }
            #pragma unroll
            for (int mt = 0; mt < 4; mt++)
                #pragma unroll
                for (int nt = 0; nt < 4; nt++)
                    mma_tf32(acc[mt][nt], a[mt], bb[nt]);
        }
    }

    float* outp = g_hparts[blockIdx.z];
    #pragma unroll
    for (int mt = 0; mt < 4; mt++){
        #pragma unroll
        for (int nt = 0; nt < 4; nt++){
            int r = mbase + wm*64 + mt*16 + (lane >> 2);
            int c = nbase + wn*32 + nt*8 + 2*(lane & 3);
            *(float2*)&outp[(size_t)r*HID + c]     = make_float2(acc[mt][nt][0], acc[mt][nt][1]);
            *(float2*)&outp[(size_t)(r+8)*HID + c] = make_float2(acc[mt][nt][2], acc[mt][nt][3]);
        }
    }
}

// ---------------- 3. split-K reduce + bias + ReLU ----------------
__global__ void bias_relu_kernel(const float* __restrict__ bfc){
    int i = blockIdx.x*blockDim.x + threadIdx.x;
    if (i < MBOX*HID){
        float s = 0.f;
        #pragma unroll
        for (int z = 0; z < SPLITK; z++) s += g_hparts[z][i];
        g_h[i] = fmaxf(s + bfc[i & (HID-1)], 0.f);
    }
}

// ---------------- 4. conv3x3 + ReLU + spatial mean (PCH=9, 32-bit P loads) --------
__global__ __launch_bounds__(512,1) void conv_kernel(const float* __restrict__ bc)
{
    int m = blockIdx.y;
    int obase = blockIdx.x * BO;
    extern __shared__ float csm[];
    float* bufW[2] = { csm,           csm + W_BUF };
    float* bufP[2] = { csm + 2*W_BUF, csm + 2*W_BUF + P_BUF };
    float* s_sum   = csm + 2*W_BUF + 2*P_BUF;

    int tid = threadIdx.x, lane = tid & 31, warp = tid >> 5;
    int wO = warp >> 2, wN = warp & 3;

    if (tid < BO) s_sum[tid] = 0.f;

    int nofs[7];
    #pragma unroll
    for (int nt = 0; nt < 7; nt++){
        int n = wN*56 + nt*8 + (lane >> 2);
        if (n < PP){
            int y = n / POOLSZ, x = n - POOLSZ*y;
            nofs[nt] = y*16 + x;
        } else nofs[nt] = 0;   // dummy; columns discarded in epilogue
    }

    float acc[2][7][4];
    #pragma unroll
    for (int i = 0; i < 2; i++)
        #pragma unroll
        for (int j = 0; j < 7; j++)
            #pragma unroll
            for (int q = 0; q < 4; q++) acc[i][j][q] = 0.f;

    const float* wsrc = g_wT + (size_t)obase*4608;
    const float* psrc = g_pp + (size_t)m*64*P_BUF;

    // slab async load: weights 2304 chunks + pooled 576 chunks (9216 B)
    auto issue_slab = [&](int bi, int s){
        for (int cid = tid; cid < 2880; cid += 512){
            if (cid < 2304){
                int row = cid / 18, c16 = (cid - row*18)*4;
                cpasync16(sptr(bufW[bi] + row*WROW + c16),
                          wsrc + (size_t)row*4608 + s*72 + c16);
            } else {
                int pc = cid - 2304;
                cpasync16(sptr(bufP[bi] + pc*4),
                          psrc + (size_t)s*P_BUF + pc*4);
            }
        }
        cp_commit();
    };

    issue_slab(0, 0);

    for (int s = 0; s < 64; s++){
        cp_wait0();
        __syncthreads();
        if (s + 1 < 64) issue_slab((s+1) & 1, s+1);

        const unsigned* cW = (const unsigned*)bufW[s & 1];
        const unsigned* cP = (const unsigned*)bufP[s & 1];
        int ch2 = (lane & 3)*2;
        #pragma unroll
        for (int tap = 0; tap < 9; tap++){
            unsigned a[2][4];
            #pragma unroll
            for (int mt = 0; mt < 2; mt++){
                int r = wO*32 + mt*16 + (lane >> 2);
                uint2 lo = *(const uint2*)&cW[(r  )*WROW + tap*8 + ch2];
                uint2 hi = *(const uint2*)&cW[(r+8)*WROW + tap*8 + ch2];
                a[mt][0] = lo.x; a[mt][2] = lo.y;
                a[mt][1] = hi.x; a[mt][3] = hi.y;
            }
            int koff = (tap/3)*16 + (tap - 3*(tap/3));
            #pragma unroll
            for (int nt = 0; nt < 7; nt++){
                int pidx = (nofs[nt] + koff)*PCH + ch2;   // may be odd -> 32-bit loads
                unsigned bb[2];
                bb[0] = cP[pidx];
                bb[1] = cP[pidx + 1];
                mma_tf32(acc[0][nt], a[0], bb);
                mma_tf32(acc[1][nt], a[1], bb);
            }
        }
    }

    // epilogue: ReLU(z + bias), sum over valid spatial, reduce
    #pragma unroll
    for (int mt = 0; mt < 2; mt++){
        int rrel = wO*32 + mt*16 + (lane >> 2);
        float bv0 = bc[obase + rrel], bv1 = bc[obase + rrel + 8];
        float s0 = 0.f, s1 = 0.f;
        #pragma unroll
        for (int nt = 0; nt < 7; nt++){
            #pragma unroll
            for (int j = 0; j < 2; j++){
                int n = wN*56 + nt*8 + 2*(lane & 3) + j;
                if (n < PP){
                    s0 += fmaxf(acc[mt][nt][j]   + bv0, 0.f);
                    s1 += fmaxf(acc[mt][nt][2+j] + bv1, 0.f);
                }
            }
        }
        s0 += __shfl_xor_sync(0xffffffffu, s0, 1);
        s0 += __shfl_xor_sync(0xffffffffu, s0, 2);
        s1 += __shfl_xor_sync(0xffffffffu, s1, 1);
        s1 += __shfl_xor_sync(0xffffffffu, s1, 2);
        if ((lane & 3) == 0){
            atomicAdd(&s_sum[rrel    ], s0);
            atomicAdd(&s_sum[rrel + 8], s1);
        }
    }
    __syncthreads();
    if (tid < BO)
        g_meanz[(size_t)m*CONVO + obase + tid] = s_sum[tid] * (1.0f/196.0f);
}

// ---------------- 5. cls/box heads + softmax ----------------
__global__ void clsbox_kernel(const float* __restrict__ wc, const float* __restrict__ bcl,
                              const float* __restrict__ wb, const float* __restrict__ bb,
                              float* __restrict__ out)
{
    int m = blockIdx.x, tid = threadIdx.x;
    __shared__ float sh[HID];
    __shared__ float sl[NCLS];
    __shared__ float s_red[4];
    for (int i = tid; i < HID; i += blockDim.x) sh[i] = g_h[(size_t)m*HID + i];
    __syncthreads();
    if (tid < NCLS){
        float ac = 0.f, ab = 0.f;
        for (int k = 0; k < HID; k++){
            float hv = sh[k];
            ac = fmaf(wc[k*NCLS + tid], hv, ac);
            ab = fmaf(wb[k*NCLS + tid], hv, ab);
        }
        sl[tid] = ac + bcl[tid];
        out[MBOX*NCLS + m*NCLS + tid] = ab + bb[tid];
    }
    __syncthreads();
    {
        float v = (tid < NCLS) ? sl[tid] : -1e30f;
        float mx = v;
        #pragma unroll
        for (int o = 16; o > 0; o >>= 1) mx = fmaxf(mx, __shfl_xor_sync(0xffffffffu, mx, o));
        if ((tid & 31) == 0) s_red[tid >> 5] = mx;
        __syncthreads();
        float gmx = fmaxf(fmaxf(s_red[0], s_red[1]), fmaxf(s_red[2], s_red[3]));
        float e = (tid < NCLS) ? expf(v - gmx) : 0.f;
        float sm = e;
        #pragma unroll
        for (int o = 16; o > 0; o >>= 1) sm += __shfl_xor_sync(0xffffffffu, sm, o);
        __syncthreads();
        if ((tid & 31) == 0) s_red[tid >> 5] = sm;
        __syncthreads();
        float gsm = s_red[0] + s_red[1] + s_red[2] + s_red[3];
        if (tid < NCLS)
            out[m*NCLS + tid] = e / gsm;
    }
}

// ---------------- 6. mask head ----------------
__global__ void mask_kernel(const float* __restrict__ wm, const float* __restrict__ bm,
                            float* __restrict__ out)
{
    int m = blockIdx.x, tid = threadIdx.x;
    __shared__ float sz[CONVO];
    for (int i = tid; i < CONVO; i += blockDim.x) sz[i] = g_meanz[(size_t)m*CONVO + i];
    __syncthreads();
    if (tid < NCLS){
        float a = 0.f;
        for (int k = 0; k < CONVO; k++) a = fmaf(wm[k*NCLS + tid], sz[k], a);
        a += bm[tid];
        out[2*MBOX*NCLS + m*NCLS + tid] = 1.f / (1.f + expf(-a));
    }
}

// ---------------- launch ----------------
extern "C" void kernel_launch(void* const* d_in, const int* in_sizes, int n_in,
                              void* d_out, int out_size)
{
    const float* p2     = (const float*)d_in[0];
    const float* p3     = (const float*)d_in[1];
    const float* p4     = (const float*)d_in[2];
    const float* p5     = (const float*)d_in[3];
    const float* boxes  = (const float*)d_in[4];
    const int*   bidx   = (const int*)  d_in[5];
    const float* w_fc1  = (const float*)d_in[6];
    const float* b_fc1  = (const float*)d_in[7];
    const float* w_cls  = (const float*)d_in[8];
    const float* b_cls  = (const float*)d_in[9];
    const float* w_box  = (const float*)d_in[10];
    const float* b_box  = (const float*)d_in[11];
    const float* w_conv = (const float*)d_in[12];
    const float* b_conv = (const float*)d_in[13];
    const float* w_mfc  = (const float*)d_in[14];
    const float* b_mfc  = (const float*)d_in[15];
    const int*   imh    = (const int*)  d_in[16];
    const int*   imw    = (const int*)  d_in[17];
    float* out = (float*)d_out;

    cudaFuncSetAttribute(fc1_kernel, cudaFuncAttributeMaxDynamicSharedMemorySize,
                         FC1_SMEM_BYTES);
    cudaFuncSetAttribute(conv_kernel, cudaFuncAttributeMaxDynamicSharedMemorySize,
                         CONV_SMEM_BYTES);

    // conv kept at launch idx 3 (the slot ncu captures)
    roialign_kernel<<<dim3(MBOX, CCH/32), 256>>>(p2, p3, p4, p5, boxes, bidx, imh, imw);
    fc1_kernel<<<dim3(MBOX/BM, HID/BN, SPLITK), 256, FC1_SMEM_BYTES>>>(w_fc1);
    wtrans_kernel<<<(CONVO*4608 + 255)/256, 256>>>(w_conv);
    conv_kernel<<<dim3(CONVO/BO, MBOX), 512, CONV_SMEM_BYTES>>>(b_conv);
    bias_relu_kernel<<<(MBOX*HID + 255)/256, 256>>>(b_fc1);
    clsbox_kernel<<<MBOX, 128>>>(w_cls, b_cls, w_box, b_box, out);
    mask_kernel<<<MBOX, 128>>>(w_mfc, b_mfc, out);
}

// round 11
// speedup vs baseline: 1.1080x; 1.1080x over previous
#include <cuda_runtime.h>
#include <math.h>

#define MBOX 512
#define CCH 512
#define POOLSZ 14
#define PP 196
#define HID 1024
#define NCLS 81
#define CONVO 256
#define KFC (CCH*PP)   /* 100352 */

#define BM 128
#define BN 128
#define BK 32
#define SPLITK 8
#define KPS (KFC/SPLITK)   /* 12544 */
#define KITERS (KPS/BK)    /* 392 */

#define BO 64   /* conv output-channel tile (halved for 2 CTA/SM occupancy) */

/* fc1 smem */
#define SA_STRIDE 36
#define SB_STRIDE 136
#define SA_BUF (BM*SA_STRIDE)
#define SB_BUF (BK*SB_STRIDE)
#define FC1_SMEM_BYTES ((2*SA_BUF + 2*SB_BUF)*4)   /* 71680 B */

/* conv smem: R7-proven layout (PCH=8, uint2 fragment loads) */
#define WROW 76
#define W_BUF (BO*WROW)              /* 4864 floats */
#define PCH 8
#define P_BUF (256*PCH)              /* 2048 floats = 8192 B per slab */
#define CONV_SMEM_BYTES ((2*W_BUF + 2*P_BUF + BO)*4)  /* 55552 B */

// ---------------- scratch (static device globals) ----------------
__device__ float g_pooled[(size_t)MBOX*CCH*PP];        // tf32-rounded, flat (fc1)
__device__ float g_pp[(size_t)MBOX*64*256*PCH];        // tf32-rounded, [slab][pos][chperm]
__device__ float g_wT[(size_t)CONVO*4608];             // tf32-rounded, [o][slab][tap][chperm]
__device__ float g_hparts[SPLITK][(size_t)MBOX*HID];
__device__ float g_h[MBOX*HID];
__device__ float g_meanz[MBOX*CONVO];

// ---------------- helpers ----------------
__device__ __forceinline__ float tf32f(float x){
    unsigned u; asm("cvt.rna.tf32.f32 %0, %1;" : "=r"(u) : "f"(x));
    return __uint_as_float(u);
}
__device__ __forceinline__ unsigned tf32u(float x){
    unsigned u; asm("cvt.rna.tf32.f32 %0, %1;" : "=r"(u) : "f"(x));
    return u;
}
__device__ __forceinline__ void mma_tf32(float* c, const unsigned* a, const unsigned* b){
    asm volatile("mma.sync.aligned.m16n8k8.row.col.f32.tf32.tf32.f32 "
                 "{%0,%1,%2,%3},{%4,%5,%6,%7},{%8,%9},{%0,%1,%2,%3};\n"
                 : "+f"(c[0]), "+f"(c[1]), "+f"(c[2]), "+f"(c[3])
                 : "r"(a[0]), "r"(a[1]), "r"(a[2]), "r"(a[3]),
                   "r"(b[0]), "r"(b[1]));
}
__device__ __forceinline__ unsigned sptr(const void* p){
    return (unsigned)__cvta_generic_to_shared(p);
}
__device__ __forceinline__ void cpasync16(unsigned dst, const float* src){
    asm volatile("cp.async.cg.shared.global [%0], [%1], 16;" :: "r"(dst), "l"(src));
}
__device__ __forceinline__ void cp_commit(){ asm volatile("cp.async.commit_group;"); }
__device__ __forceinline__ void cp_wait0(){ asm volatile("cp.async.wait_group 0;"); }

__device__ __forceinline__ int chperm_of(int ch){ return (ch & 3)*2 + (ch >> 2); }

// ---------------- 1. RoIAlign (dual-layout write, pre-rounded; R7 version) --------
__global__ void roialign_kernel(const float* __restrict__ p2, const float* __restrict__ p3,
                                const float* __restrict__ p4, const float* __restrict__ p5,
                                const float* __restrict__ boxes, const int* __restrict__ bidx,
                                const int* __restrict__ imh, const int* __restrict__ imw)
{
    int m = blockIdx.x;
    int cbase = blockIdx.y * 32;
    __shared__ float s_lx[POOLSZ], s_ly[POOLSZ];
    __shared__ int   s_x0[POOLSZ], s_x1[POOLSZ], s_y0[POOLSZ], s_y1[POOLSZ];
    __shared__ const float* s_feat;
    __shared__ int s_H, s_W;
    int tid = threadIdx.x;

    if (tid == 0){
        float bx1 = boxes[m*4+0], by1 = boxes[m*4+1];
        float bx2 = boxes[m*4+2], by2 = boxes[m*4+3];
        int hv = imh[0], wv = imw[0];
        float alpha = 224.0f/800.0f * (float)min(hv, wv);
        float bw = fabsf(bx2-bx1), bh = fabsf(by2-by1);
        float s  = sqrtf(fmaxf(bw*bh, 1e-6f));
        float kf = floorf(4.0f + log2f(s/alpha));
        int lvl  = (int)fminf(fmaxf(kf - 2.0f, 0.0f), 3.0f);
        const float* fp; int H, W; float scale;
        if      (lvl == 0){ fp = p2; H = 200; W = 200; scale = 0.25f; }
        else if (lvl == 1){ fp = p3; H = 100; W = 100; scale = 0.125f; }
        else if (lvl == 2){ fp = p4; H = 50;  W = 50;  scale = 0.0625f; }
        else              { fp = p5; H = 25;  W = 25;  scale = 0.03125f; }
        s_feat = fp; s_H = H; s_W = W;
        float sx1 = bx1*scale, sx2 = bx2*scale, sy1 = by1*scale, sy2 = by2*scale;
        for (int i = 0; i < POOLSZ; i++){
            float g  = ((float)i + 0.5f) / (float)POOLSZ;
            float xs = sx1 + g*(sx2 - sx1);
            float x0f = floorf(xs);
            s_lx[i] = xs - x0f;
            s_x0[i] = min(max((int)x0f, 0), W-1);
            s_x1[i] = min(max((int)x0f + 1, 0), W-1);
            float ys = sy1 + g*(sy2 - sy1);
            float y0f = floorf(ys);
            s_ly[i] = ys - y0f;
            s_y0[i] = min(max((int)y0f, 0), H-1);
            s_y1[i] = min(max((int)y0f + 1, 0), H-1);
        }
    }
    __syncthreads();

    const float* f = s_feat;
    int H = s_H, W = s_W;
    int b = bidx[m];

    // zero padded borders (all 256 positions' borders for these 32 channels)
    for (int e = tid; e < 32*256; e += blockDim.x){
        int ch = e >> 8, p = e & 255;
        int ty = p >> 4, tx = p & 15;
        if (ty == 0 || ty == 15 || tx == 0 || tx == 15){
            int c = cbase + ch;
            g_pp[(((size_t)m*64 + (c>>3))*256 + p)*PCH + chperm_of(c&7)] = 0.f;
        }
    }

    for (int e = tid; e < 32*PP; e += blockDim.x){
        int cl  = e / PP;
        int bin = e - cl*PP;
        int py  = bin / POOLSZ, px = bin - py*POOLSZ;
        int c   = cbase + cl;
        const float* fb = f + ((size_t)(b*CCH + c)) * H * W;
        float lx = s_lx[px], ly = s_ly[py];
        int x0 = s_x0[px], x1 = s_x1[px], y0 = s_y0[py], y1 = s_y1[py];
        float f00 = fb[y0*W + x0], f01 = fb[y0*W + x1];
        float f10 = fb[y1*W + x0], f11 = fb[y1*W + x1];
        float v = f00*(1.f-ly)*(1.f-lx) + f01*(1.f-ly)*lx
                + f10*ly*(1.f-lx)       + f11*ly*lx;
        float vr = tf32f(v);
        g_pooled[((size_t)m*CCH + c)*PP + bin] = vr;
        int pos = (py+1)*16 + (px+1);
        g_pp[(((size_t)m*64 + (c>>3))*256 + pos)*PCH + chperm_of(c&7)] = vr;
    }
}

// ---------------- 1b. conv weights: tap-major + k-pair interleave + tf32 round -----
__global__ void wtrans_kernel(const float* __restrict__ Wc){
    int i = blockIdx.x*256 + threadIdx.x;
    if (i < CONVO*4608){
        int o = i / 4608, k = i - o*4608;
        int slab = k / 72, r = k - slab*72;
        int tap = r >> 3, cp = r & 7;
        int ch = (cp >> 1) | ((cp & 1) << 2);
        g_wT[i] = tf32f(Wc[(size_t)o*4608 + (slab*8 + ch)*9 + tap]);
    }
}

// ---------------- 2. FC1 GEMM (tf32, cp.async double-buffered, split-K slices) -----
__global__ __launch_bounds__(256,2) void fc1_kernel(const float* __restrict__ Bw)
{
    extern __shared__ float sm[];
    float* bufA[2] = { sm,            sm + SA_BUF };
    float* bufB[2] = { sm + 2*SA_BUF, sm + 2*SA_BUF + SB_BUF };

    int tid = threadIdx.x, lane = tid & 31, warp = tid >> 5;
    int wm = warp >> 2, wn = warp & 3;
    int mbase = blockIdx.x * BM;
    int nbase = blockIdx.y * BN;
    int k0    = blockIdx.z * KPS;

    float acc[4][4][4];
    #pragma unroll
    for (int i = 0; i < 4; i++)
        #pragma unroll
        for (int j = 0; j < 4; j++)
            #pragma unroll
            for (int q = 0; q < 4; q++) acc[i][j][q] = 0.f;

    auto issue_tile = [&](int bi, int it){
        int koff = k0 + it*BK;
        #pragma unroll
        for (int j = 0; j < 4; j++){
            int cid = tid + j*256;
            int row = cid >> 3, c16 = (cid & 7)*4;
            cpasync16(sptr(bufA[bi] + row*SA_STRIDE + c16),
                      g_pooled + (size_t)(mbase+row)*KFC + koff + c16);
        }
        #pragma unroll
        for (int j = 0; j < 4; j++){
            int cid = tid + j*256;
            int row = cid >> 5, c16 = (cid & 31)*4;
            cpasync16(sptr(bufB[bi] + row*SB_STRIDE + c16),
                      Bw + (size_t)(koff+row)*HID + nbase + c16);
        }
        cp_commit();
    };

    issue_tile(0, 0);

    for (int it = 0; it < KITERS; it++){
        cp_wait0();
        __syncthreads();
        if (it + 1 < KITERS) issue_tile((it+1) & 1, it+1);

        const unsigned* cA = (const unsigned*)bufA[it & 1];
        const float*    cB = bufB[it & 1];
        #pragma unroll
        for (int ks = 0; ks < 4; ks++){
            unsigned a[4][4], bb[4][2];
            int kc = ks*8 + (lane & 3);
            #pragma unroll
            for (int mt = 0; mt < 4; mt++){
                int r = wm*64 + mt*16 + (lane >> 2);
                a[mt][0] = cA[(r  )*SA_STRIDE + kc  ];
                a[mt][1] = cA[(r+8)*SA_STRIDE + kc  ];
                a[mt][2] = cA[(r  )*SA_STRIDE + kc+4];
                a[mt][3] = cA[(r+8)*SA_STRIDE + kc+4];
            }
            #pragma unroll
            for (int nt = 0; nt < 4; nt++){
                int cidx = wn*32 + nt*8 + (lane >> 2);
                bb[nt][0] = tf32u(cB[(kc  )*SB_STRIDE + cidx]);
                bb[nt][1] = tf32u(cB[(kc+4)*SB_STRIDE + cidx]);
            }
            #pragma unroll
            for (int mt = 0; mt < 4; mt++)
                #pragma unroll
                for (int nt = 0; nt < 4; nt++)
                    mma_tf32(acc[mt][nt], a[mt], bb[nt]);
        }
    }

    float* outp = g_hparts[blockIdx.z];
    #pragma unroll
    for (int mt = 0; mt < 4; mt++){
        #pragma unroll
        for (int nt = 0; nt < 4; nt++){
            int r = mbase + wm*64 + mt*16 + (lane >> 2);
            int c = nbase + wn*32 + nt*8 + 2*(lane & 3);
            *(float2*)&outp[(size_t)r*HID + c]     = make_float2(acc[mt][nt][0], acc[mt][nt][1]);
            *(float2*)&outp[(size_t)(r+8)*HID + c] = make_float2(acc[mt][nt][2], acc[mt][nt][3]);
        }
    }
}

// ---------------- 3. split-K reduce + bias + ReLU ----------------
__global__ void bias_relu_kernel(const float* __restrict__ bfc){
    int i = blockIdx.x*blockDim.x + threadIdx.x;
    if (i < MBOX*HID){
        float s = 0.f;
        #pragma unroll
        for (int z = 0; z < SPLITK; z++) s += g_hparts[z][i];
        g_h[i] = fmaxf(s + bfc[i & (HID-1)], 0.f);
    }
}

// ---------------- 4. conv3x3 + ReLU + spatial mean (R7 data path, 2 CTA/SM) -------
__global__ __launch_bounds__(256,2) void conv_kernel(const float* __restrict__ bc)
{
    int m = blockIdx.y;
    int obase = blockIdx.x * BO;
    extern __shared__ float csm[];
    float* bufW[2] = { csm,           csm + W_BUF };
    float* bufP[2] = { csm + 2*W_BUF, csm + 2*W_BUF + P_BUF };
    float* s_sum   = csm + 2*W_BUF + 2*P_BUF;

    int tid = threadIdx.x, lane = tid & 31, warp = tid >> 5;
    int wO = warp >> 2, wN = warp & 3;     // 2x4 warp grid, warp tile 32(o) x 56(spatial)

    if (tid < BO) s_sum[tid] = 0.f;

    int nofs[7];
    #pragma unroll
    for (int nt = 0; nt < 7; nt++){
        int n = wN*56 + nt*8 + (lane >> 2);
        if (n < PP){
            int y = n / POOLSZ, x = n - POOLSZ*y;
            nofs[nt] = y*16 + x;
        } else nofs[nt] = 0;   // dummy; columns discarded in epilogue
    }

    float acc[2][7][4];
    #pragma unroll
    for (int i = 0; i < 2; i++)
        #pragma unroll
        for (int j = 0; j < 7; j++)
            #pragma unroll
            for (int q = 0; q < 4; q++) acc[i][j][q] = 0.f;

    const float* wsrc = g_wT + (size_t)obase*4608;
    const float* psrc = g_pp + (size_t)m*64*P_BUF;

    // slab async load: weights 1152 chunks + pooled 512 chunks
    auto issue_slab = [&](int bi, int s){
        for (int cid = tid; cid < 1664; cid += 256){
            if (cid < 1152){
                int row = cid / 18, c16 = (cid - row*18)*4;
                cpasync16(sptr(bufW[bi] + row*WROW + c16),
                          wsrc + (size_t)row*4608 + s*72 + c16);
            } else {
                int pc = cid - 1152;
                cpasync16(sptr(bufP[bi] + pc*4),
                          psrc + (size_t)s*P_BUF + pc*4);
            }
        }
        cp_commit();
    };

    issue_slab(0, 0);

    for (int s = 0; s < 64; s++){
        cp_wait0();
        __syncthreads();
        if (s + 1 < 64) issue_slab((s+1) & 1, s+1);

        const unsigned* cW = (const unsigned*)bufW[s & 1];
        const unsigned* cP = (const unsigned*)bufP[s & 1];
        int ch2 = (lane & 3)*2;
        #pragma unroll
        for (int tap = 0; tap < 9; tap++){
            unsigned a[2][4];
            #pragma unroll
            for (int mt = 0; mt < 2; mt++){
                int r = wO*32 + mt*16 + (lane >> 2);
                uint2 lo = *(const uint2*)&cW[(r  )*WROW + tap*8 + ch2];
                uint2 hi = *(const uint2*)&cW[(r+8)*WROW + tap*8 + ch2];
                a[mt][0] = lo.x; a[mt][2] = lo.y;
                a[mt][1] = hi.x; a[mt][3] = hi.y;
            }
            int koff = (tap/3)*16 + (tap - 3*(tap/3));
            #pragma unroll
            for (int nt = 0; nt < 7; nt++){
                uint2 bp = *(const uint2*)&cP[(nofs[nt] + koff)*PCH + ch2];
                unsigned bb[2] = { bp.x, bp.y };
                mma_tf32(acc[0][nt], a[0], bb);
                mma_tf32(acc[1][nt], a[1], bb);
            }
        }
    }

    // epilogue: ReLU(z + bias), sum over valid spatial, reduce
    #pragma unroll
    for (int mt = 0; mt < 2; mt++){
        int rrel = wO*32 + mt*16 + (lane >> 2);
        float bv0 = bc[obase + rrel], bv1 = bc[obase + rrel + 8];
        float s0 = 0.f, s1 = 0.f;
        #pragma unroll
        for (int nt = 0; nt < 7; nt++){
            #pragma unroll
            for (int j = 0; j < 2; j++){
                int n = wN*56 + nt*8 + 2*(lane & 3) + j;
                if (n < PP){
                    s0 += fmaxf(acc[mt][nt][j]   + bv0, 0.f);
                    s1 += fmaxf(acc[mt][nt][2+j] + bv1, 0.f);
                }
            }
        }
        s0 += __shfl_xor_sync(0xffffffffu, s0, 1);
        s0 += __shfl_xor_sync(0xffffffffu, s0, 2);
        s1 += __shfl_xor_sync(0xffffffffu, s1, 1);
        s1 += __shfl_xor_sync(0xffffffffu, s1, 2);
        if ((lane & 3) == 0){
            atomicAdd(&s_sum[rrel    ], s0);
            atomicAdd(&s_sum[rrel + 8], s1);
        }
    }
    __syncthreads();
    if (tid < BO)
        g_meanz[(size_t)m*CONVO + obase + tid] = s_sum[tid] * (1.0f/196.0f);
}

// ---------------- 5. cls/box heads + softmax ----------------
__global__ void clsbox_kernel(const float* __restrict__ wc, const float* __restrict__ bcl,
                              const float* __restrict__ wb, const float* __restrict__ bb,
                              float* __restrict__ out)
{
    int m = blockIdx.x, tid = threadIdx.x;
    __shared__ float sh[HID];
    __shared__ float sl[NCLS];
    __shared__ float s_red[4];
    for (int i = tid; i < HID; i += blockDim.x) sh[i] = g_h[(size_t)m*HID + i];
    __syncthreads();
    if (tid < NCLS){
        float ac = 0.f, ab = 0.f;
        for (int k = 0; k < HID; k++){
            float hv = sh[k];
            ac = fmaf(wc[k*NCLS + tid], hv, ac);
            ab = fmaf(wb[k*NCLS + tid], hv, ab);
        }
        sl[tid] = ac + bcl[tid];
        out[MBOX*NCLS + m*NCLS + tid] = ab + bb[tid];
    }
    __syncthreads();
    {
        float v = (tid < NCLS) ? sl[tid] : -1e30f;
        float mx = v;
        #pragma unroll
        for (int o = 16; o > 0; o >>= 1) mx = fmaxf(mx, __shfl_xor_sync(0xffffffffu, mx, o));
        if ((tid & 31) == 0) s_red[tid >> 5] = mx;
        __syncthreads();
        float gmx = fmaxf(fmaxf(s_red[0], s_red[1]), fmaxf(s_red[2], s_red[3]));
        float e = (tid < NCLS) ? expf(v - gmx) : 0.f;
        float sm = e;
        #pragma unroll
        for (int o = 16; o > 0; o >>= 1) sm += __shfl_xor_sync(0xffffffffu, sm, o);
        __syncthreads();
        if ((tid & 31) == 0) s_red[tid >> 5] = sm;
        __syncthreads();
        float gsm = s_red[0] + s_red[1] + s_red[2] + s_red[3];
        if (tid < NCLS)
            out[m*NCLS + tid] = e / gsm;
    }
}

// ---------------- 6. mask head ----------------
__global__ void mask_kernel(const float* __restrict__ wm, const float* __restrict__ bm,
                            float* __restrict__ out)
{
    int m = blockIdx.x, tid = threadIdx.x;
    __shared__ float sz[CONVO];
    for (int i = tid; i < CONVO; i += blockDim.x) sz[i] = g_meanz[(size_t)m*CONVO + i];
    __syncthreads();
    if (tid < NCLS){
        float a = 0.f;
        for (int k = 0; k < CONVO; k++) a = fmaf(wm[k*NCLS + tid], sz[k], a);
        a += bm[tid];
        out[2*MBOX*NCLS + m*NCLS + tid] = 1.f / (1.f + expf(-a));
    }
}

// ---------------- launch ----------------
extern "C" void kernel_launch(void* const* d_in, const int* in_sizes, int n_in,
                              void* d_out, int out_size)
{
    const float* p2     = (const float*)d_in[0];
    const float* p3     = (const float*)d_in[1];
    const float* p4     = (const float*)d_in[2];
    const float* p5     = (const float*)d_in[3];
    const float* boxes  = (const float*)d_in[4];
    const int*   bidx   = (const int*)  d_in[5];
    const float* w_fc1  = (const float*)d_in[6];
    const float* b_fc1  = (const float*)d_in[7];
    const float* w_cls  = (const float*)d_in[8];
    const float* b_cls  = (const float*)d_in[9];
    const float* w_box  = (const float*)d_in[10];
    const float* b_box  = (const float*)d_in[11];
    const float* w_conv = (const float*)d_in[12];
    const float* b_conv = (const float*)d_in[13];
    const float* w_mfc  = (const float*)d_in[14];
    const float* b_mfc  = (const float*)d_in[15];
    const int*   imh    = (const int*)  d_in[16];
    const int*   imw    = (const int*)  d_in[17];
    float* out = (float*)d_out;

    cudaFuncSetAttribute(fc1_kernel, cudaFuncAttributeMaxDynamicSharedMemorySize,
                         FC1_SMEM_BYTES);
    cudaFuncSetAttribute(conv_kernel, cudaFuncAttributeMaxDynamicSharedMemorySize,
                         CONV_SMEM_BYTES);

    // conv kept at launch idx 3 (the slot ncu captures)
    roialign_kernel<<<dim3(MBOX, CCH/32), 256>>>(p2, p3, p4, p5, boxes, bidx, imh, imw);
    fc1_kernel<<<dim3(MBOX/BM, HID/BN, SPLITK), 256, FC1_SMEM_BYTES>>>(w_fc1);
    wtrans_kernel<<<(CONVO*4608 + 255)/256, 256>>>(w_conv);
    conv_kernel<<<dim3(CONVO/BO, MBOX), 256, CONV_SMEM_BYTES>>>(b_conv);
    bias_relu_kernel<<<(MBOX*HID + 255)/256, 256>>>(b_fc1);
    clsbox_kernel<<<MBOX, 128>>>(w_cls, b_cls, w_box, b_box, out);
    mask_kernel<<<MBOX, 128>>>(w_mfc, b_mfc, out);
}